// round 6
// baseline (speedup 1.0000x reference)
#include <cuda_runtime.h>
#include <math.h>

__device__ float g_m1[4096];
__device__ float g_m2[4096];
__device__ float g_pots[125829120];   // [B*T, 2048]
__device__ float g_scores[61440];     // [B*T]
__device__ float g_ctx[8388608];      // [B, 2048]

// ---------------- K0: dynamic Laplacian masks ----------------
__global__ __launch_bounds__(256)
void k0_masks(const float* __restrict__ mask1, const float* __restrict__ mask2) {
    int idx = blockIdx.x * 256 + threadIdx.x;
    int i = idx >> 6, j = idx & 63;
    float a = mask1[i * 64 + j] + mask1[j * 64 + i];
    g_m1[idx] = 0.5f / (1.f + expf(-a));
    float c = mask2[i * 64 + j] + mask2[j * 64 + i];
    g_m2[idx] = 0.5f / (1.f + expf(-c));
}

// ---------------- K1: per-batch conv+BN + 15-step SNN ----------------
// dyn smem floats: sL1@0(64x65) sL2@4160 sx@8320(960) sy@9280(960)
// spar@10240(704) memt@10944 spkt@11008 scr@11072(3840) mg2@14912(2048) = 16960
__global__ __launch_bounds__(256, 3)
void k1_snn(const float* __restrict__ L_norm, const float* __restrict__ X_seq,
            const float* __restrict__ conv_w, const float* __restrict__ conv_b,
            const float* __restrict__ bn_gamma, const float* __restrict__ bn_beta,
            const float* __restrict__ bn_mean, const float* __restrict__ bn_var,
            const float* __restrict__ gcn1_w, const float* __restrict__ gcn1_b,
            const float* __restrict__ gcn2_w, const float* __restrict__ gcn2_b,
            const float* __restrict__ beta2p)
{
    extern __shared__ float sm[];
    float* sL1 = sm;           float* sL2 = sm + 4160;
    float* sx = sm + 8320;     float* sy = sm + 9280;
    float* spar = sm + 10240;  float* s_memt = sm + 10944;
    float* s_spkt = sm + 11008; float* s_scr = sm + 11072;
    float* s_mg1 = s_scr;       float* s_spk1 = s_scr + 1024;
    float* s_A = s_scr + 2048;  float* s_part = s_scr + 3072;
    float* s_mg2 = sm + 14912;

    const int tid = threadIdx.x;
    const int b = blockIdx.x;
    const float bt2 = beta2p[0];

    for (int i = tid; i < 960; i += 256) sx[i] = X_seq[(size_t)b * 960 + i];
    const float* Lb = L_norm + (size_t)b * 4096;
    for (int i = tid; i < 4096; i += 256) {
        float l = Lb[i];
        int r = i >> 6, c = i & 63;
        sL1[r * 65 + c] = l * g_m1[i];
        sL2[r * 65 + c] = l * g_m2[i];
    }
    if (tid < 16) { spar[tid] = gcn1_w[tid]; spar[16 + tid] = gcn1_b[tid]; }
    for (int i = tid; i < 512; i += 256) spar[32 + i] = gcn2_w[i];
    if (tid < 32) spar[544 + tid] = gcn2_b[tid];
    if (tid < 64) {
        float cs = bn_gamma[tid] * rsqrtf(bn_var[tid] + 1e-5f);
        spar[576 + tid] = cs;
        spar[640 + tid] = bn_beta[tid] + (conv_b[tid] - bn_mean[tid]) * cs;
    }
    __syncthreads();

    // causal conv1d: 4 threads per out-channel
    {
        const int c = tid & 63, q = tid >> 6, i0 = q * 16;
        float p[15];
        #pragma unroll
        for (int t = 0; t < 15; ++t) p[t] = 0.f;
        const float* wc = conv_w + (size_t)(c * 64 + i0) * 3;
        for (int ii = 0; ii < 16; ++ii) {
            float w0 = wc[ii * 3], w1 = wc[ii * 3 + 1], w2 = wc[ii * 3 + 2];
            const float* xc = sx + (i0 + ii);
            #pragma unroll
            for (int t = 0; t < 15; ++t) {
                float a = w2 * xc[t * 64];
                if (t >= 1) a += w1 * xc[(t - 1) * 64];
                if (t >= 2) a += w0 * xc[(t - 2) * 64];
                p[t] += a;
            }
        }
        #pragma unroll
        for (int t = 0; t < 15; ++t) s_scr[q * 960 + t * 64 + c] = p[t];
    }
    __syncthreads();
    for (int i = tid; i < 960; i += 256) {
        int c = i & 63;
        float v = s_scr[i] + s_scr[960 + i] + s_scr[1920 + i] + s_scr[2880 + i];
        sy[i] = v * spar[576 + c] + spar[640 + c];
    }
    __syncthreads();

    if (tid < 64) s_memt[tid] = 0.f;
    for (int i = tid; i < 1024; i += 256) s_mg1[i] = 0.f;
    for (int i = tid; i < 2048; i += 256) s_mg2[i] = 0.f;
    __syncthreads();

    const int iA = tid >> 2, gA = tid & 3, f0 = gA * 8;

    for (int t = 0; t < 15; ++t) {
        if (tid < 64) {
            float m = s_memt[tid];
            float rst = (m > 1.f) ? 1.f : 0.f;
            m = 0.9f * m + sy[t * 64 + tid] - rst;
            s_memt[tid] = m;
            s_spkt[tid] = (m > 1.f) ? 1.f : 0.f;
        }
        __syncthreads();
        {   // s = L1 @ spk_t (4 partial groups of 16)
            int q = tid >> 6, i = tid & 63;
            float s = 0.f;
            #pragma unroll
            for (int j = 0; j < 16; ++j)
                s += sL1[i * 65 + q * 16 + j] * s_spkt[q * 16 + j];
            s_part[q * 64 + i] = s;
        }
        __syncthreads();
        #pragma unroll
        for (int v = 0; v < 4; ++v) {   // rank-1 GCN1 + LIF [64,16]
            int e = tid + v * 256;
            int i = e >> 4, f = e & 15;
            float sv = s_part[i] + s_part[64 + i] + s_part[128 + i] + s_part[192 + i];
            float cur = sv * spar[f] + spar[16 + f];
            float m = s_mg1[e];
            float rst = (m > 1.f) ? 1.f : 0.f;
            m = 0.85f * m + cur - rst;
            s_mg1[e] = m;
            s_spk1[e] = (m > 1.f) ? 1.f : 0.f;
        }
        __syncthreads();
        {   // A = L2 @ spk1  [64,64]@[64,16]
            float4 a = make_float4(0.f, 0.f, 0.f, 0.f);
            #pragma unroll
            for (int j = 0; j < 64; ++j) {
                float l = sL2[iA * 65 + j];
                float4 s4 = *(const float4*)(s_spk1 + j * 16 + gA * 4);
                a.x += l * s4.x; a.y += l * s4.y; a.z += l * s4.z; a.w += l * s4.w;
            }
            *(float4*)(s_A + iA * 16 + gA * 4) = a;
        }
        __syncthreads();
        {   // cur2 = A @ W2 + b2 ; LIF ; emit mem_g2 as pots
            float4 c0 = *(const float4*)(spar + 544 + f0);
            float4 c1 = *(const float4*)(spar + 544 + f0 + 4);
            #pragma unroll
            for (int k = 0; k < 16; ++k) {
                float av = s_A[iA * 16 + k];
                float4 wA = *(const float4*)(spar + 32 + k * 32 + f0);
                float4 wB = *(const float4*)(spar + 32 + k * 32 + f0 + 4);
                c0.x += av * wA.x; c0.y += av * wA.y; c0.z += av * wA.z; c0.w += av * wA.w;
                c1.x += av * wB.x; c1.y += av * wB.y; c1.z += av * wB.z; c1.w += av * wB.w;
            }
            float cv[8] = {c0.x, c0.y, c0.z, c0.w, c1.x, c1.y, c1.z, c1.w};
            float* mg = s_mg2 + iA * 32 + f0;
            float ov[8];
            #pragma unroll
            for (int u = 0; u < 8; ++u) {
                float m = mg[u];
                float rst = (m > 1.f) ? 1.f : 0.f;
                m = bt2 * m + cv[u] - rst;
                mg[u] = m; ov[u] = m;
            }
            float* gp = g_pots + (size_t)(b * 15 + t) * 2048 + iA * 32 + f0;
            *(float4*)gp = make_float4(ov[0], ov[1], ov[2], ov[3]);
            *(float4*)(gp + 4) = make_float4(ov[4], ov[5], ov[6], ov[7]);
        }
        __syncthreads();
    }
}

// ---------------- K2: attention scores GEMM [61440,2048]@[2048,32] ----------------
__global__ __launch_bounds__(256)
void k2_scores(const float* __restrict__ W1, const float* __restrict__ b1,
               const float* __restrict__ w2, const float* __restrict__ b2)
{
    __shared__ float sP[128 * 64];
    __shared__ float sW[64 * 32];
    const int tid = threadIdx.x;
    const size_t rb = (size_t)blockIdx.x * 128;
    const int f = tid & 31, rg = tid >> 5;
    float acc[16];
    #pragma unroll
    for (int r = 0; r < 16; ++r) acc[r] = 0.f;

    for (int kc = 0; kc < 32; ++kc) {
        __syncthreads();
        #pragma unroll
        for (int v = 0; v < 32; ++v) {
            int idx = tid + v * 256;
            sP[idx] = g_pots[(rb + (idx >> 6)) * 2048 + kc * 64 + (idx & 63)];
        }
        #pragma unroll
        for (int v = 0; v < 8; ++v) {
            int idx = tid + v * 256;
            sW[idx] = W1[(size_t)(kc * 64 + (idx >> 5)) * 32 + (idx & 31)];
        }
        __syncthreads();
        #pragma unroll
        for (int j4 = 0; j4 < 16; ++j4) {
            float w0 = sW[(j4 * 4 + 0) * 32 + f];
            float w1v = sW[(j4 * 4 + 1) * 32 + f];
            float w2v = sW[(j4 * 4 + 2) * 32 + f];
            float w3v = sW[(j4 * 4 + 3) * 32 + f];
            #pragma unroll
            for (int r = 0; r < 16; ++r) {
                float4 p = *(const float4*)(sP + (rg * 16 + r) * 64 + j4 * 4);
                acc[r] += p.x * w0 + p.y * w1v + p.z * w2v + p.w * w3v;
            }
        }
    }
    float b1f = b1[f], w2f = w2[f], b2s = b2[0];
    #pragma unroll
    for (int r = 0; r < 16; ++r) {
        float v = tanhf(acc[r] + b1f) * w2f;
        v += __shfl_xor_sync(0xffffffffu, v, 16);
        v += __shfl_xor_sync(0xffffffffu, v, 8);
        v += __shfl_xor_sync(0xffffffffu, v, 4);
        v += __shfl_xor_sync(0xffffffffu, v, 2);
        v += __shfl_xor_sync(0xffffffffu, v, 1);
        if (f == 0) g_scores[rb + rg * 16 + r] = v + b2s;
    }
}

// ---------------- K3: softmax over T + context ----------------
__global__ __launch_bounds__(256)
void k3_ctx() {
    const int b = blockIdx.x, tid = threadIdx.x;
    __shared__ float ssc[16];
    if (tid < 15) ssc[tid] = g_scores[b * 15 + tid];
    __syncthreads();
    float w[15], mx = ssc[0];
    #pragma unroll
    for (int t = 1; t < 15; ++t) mx = fmaxf(mx, ssc[t]);
    float se = 0.f;
    #pragma unroll
    for (int t = 0; t < 15; ++t) { w[t] = expf(ssc[t] - mx); se += w[t]; }
    float inv = 1.f / se;
    const float* pb = g_pots + (size_t)b * 15 * 2048;
    float* cb = g_ctx + (size_t)b * 2048;
    #pragma unroll
    for (int e8 = 0; e8 < 8; ++e8) {
        int e = tid + e8 * 256;
        float acc = 0.f;
        #pragma unroll
        for (int t = 0; t < 15; ++t) acc += w[t] * pb[t * 2048 + e];
        cb[e] = acc * inv;
    }
}

// ---------------- K4: classifier + LN + GELU + final ----------------
__global__ __launch_bounds__(256)
void k4_cls(const float* __restrict__ W1, const float* __restrict__ b1,
            const float* __restrict__ lng, const float* __restrict__ lnb,
            const float* __restrict__ W2, const float* __restrict__ b2,
            float* __restrict__ out)
{
    __shared__ float sC[16 * 68];
    __shared__ float sW[64 * 128];
    __shared__ float sH[16 * 132];
    const int tid = threadIdx.x;
    const int rb = blockIdx.x * 16;
    const int r = tid >> 4, cg = tid & 15;
    float acc[8] = {0, 0, 0, 0, 0, 0, 0, 0};

    for (int ch = 0; ch < 32; ++ch) {
        __syncthreads();
        for (int i = tid; i < 1024; i += 256) {
            int rr = i >> 6, kk = i & 63;
            sC[rr * 68 + kk] = g_ctx[(size_t)(rb + rr) * 2048 + ch * 64 + kk];
        }
        for (int i = tid; i < 8192; i += 256)
            sW[i] = W1[(size_t)(ch * 64 + (i >> 7)) * 128 + (i & 127)];
        __syncthreads();
        #pragma unroll 8
        for (int k = 0; k < 64; ++k) {
            float a = sC[r * 68 + k];
            float4 w0 = *(const float4*)(sW + k * 128 + cg * 8);
            float4 w1 = *(const float4*)(sW + k * 128 + cg * 8 + 4);
            acc[0] += a * w0.x; acc[1] += a * w0.y; acc[2] += a * w0.z; acc[3] += a * w0.w;
            acc[4] += a * w1.x; acc[5] += a * w1.y; acc[6] += a * w1.z; acc[7] += a * w1.w;
        }
    }
    __syncthreads();
    #pragma unroll
    for (int u = 0; u < 8; ++u) sH[r * 132 + cg * 8 + u] = acc[u] + b1[cg * 8 + u];
    __syncthreads();
    {
        float s = 0.f, s2 = 0.f;
        #pragma unroll
        for (int u = 0; u < 8; ++u) {
            float v = sH[r * 132 + cg * 8 + u];
            s += v; s2 += v * v;
        }
        #pragma unroll
        for (int o = 8; o >= 1; o >>= 1) {
            s += __shfl_xor_sync(0xffffffffu, s, o);
            s2 += __shfl_xor_sync(0xffffffffu, s2, o);
        }
        float mu = s * (1.f / 128.f);
        float var = s2 * (1.f / 128.f) - mu * mu;
        float rstd = rsqrtf(var + 1e-5f);
        #pragma unroll
        for (int u = 0; u < 8; ++u) {
            int c = cg * 8 + u;
            float v = (sH[r * 132 + c] - mu) * rstd * lng[c] + lnb[c];
            v = 0.5f * v * (1.f + erff(v * 0.70710678118654752440f));
            sH[r * 132 + c] = v;
        }
    }
    __syncthreads();
    if (tid < 64) {
        int rr = tid >> 2, o = tid & 3;
        float a = b2[o];
        #pragma unroll 16
        for (int c = 0; c < 128; ++c) a += sH[rr * 132 + c] * W2[c * 4 + o];
        out[(size_t)(rb + rr) * 4 + o] = a;
    }
}

extern "C" void kernel_launch(void* const* d_in, const int* in_sizes, int n_in,
                              void* d_out, int out_size) {
    (void)in_sizes; (void)n_in; (void)out_size;
    const float* L_norm  = (const float*)d_in[0];
    const float* X_seq   = (const float*)d_in[1];
    const float* conv_w  = (const float*)d_in[2];
    const float* conv_b  = (const float*)d_in[3];
    const float* bn_g    = (const float*)d_in[4];
    const float* bn_b    = (const float*)d_in[5];
    const float* bn_m    = (const float*)d_in[6];
    const float* bn_v    = (const float*)d_in[7];
    const float* g1w     = (const float*)d_in[8];
    const float* g1b     = (const float*)d_in[9];
    const float* mask1   = (const float*)d_in[10];
    const float* g2w     = (const float*)d_in[11];
    const float* g2b     = (const float*)d_in[12];
    const float* mask2   = (const float*)d_in[13];
    const float* beta2   = (const float*)d_in[14];
    const float* aw1     = (const float*)d_in[15];
    const float* ab1     = (const float*)d_in[16];
    const float* aw2     = (const float*)d_in[17];
    const float* ab2     = (const float*)d_in[18];
    const float* cw1     = (const float*)d_in[19];
    const float* cb1     = (const float*)d_in[20];
    const float* lng     = (const float*)d_in[21];
    const float* lnb     = (const float*)d_in[22];
    const float* cw2     = (const float*)d_in[23];
    const float* cb2     = (const float*)d_in[24];
    float* out = (float*)d_out;

    cudaFuncSetAttribute(k1_snn, cudaFuncAttributeMaxDynamicSharedMemorySize, 16960 * 4);

    k0_masks<<<16, 256>>>(mask1, mask2);
    k1_snn<<<4096, 256, 16960 * 4>>>(L_norm, X_seq, conv_w, conv_b, bn_g, bn_b,
                                     bn_m, bn_v, g1w, g1b, g2w, g2b, beta2);
    k2_scores<<<480, 256>>>(aw1, ab1, aw2, ab2);
    k3_ctx<<<4096, 256>>>();
    k4_cls<<<256, 256>>>(cw1, cb1, lng, lnb, cw2, cb2, out);
}

// round 7
// speedup vs baseline: 1.7307x; 1.7307x over previous
#include <cuda_runtime.h>
#include <math.h>

__device__ float g_m1[4096];
__device__ float g_m2[4096];
__device__ float g_pots[125829120];   // [B*T, 2048]
__device__ float g_ctx[8388608];      // [B, 2048]

// ---- packed f32x2 helpers (Blackwell) ----
__device__ __forceinline__ unsigned long long pk2(float lo, float hi) {
    unsigned long long r;
    asm("mov.b64 %0, {%1, %2};" : "=l"(r) : "f"(lo), "f"(hi));
    return r;
}
__device__ __forceinline__ void upk2(unsigned long long v, float& lo, float& hi) {
    asm("mov.b64 {%0, %1}, %2;" : "=f"(lo), "=f"(hi) : "l"(v));
}
__device__ __forceinline__ void fma2(unsigned long long& d, unsigned long long a,
                                     unsigned long long b) {
    asm("fma.rn.f32x2 %0, %1, %2, %0;" : "+l"(d) : "l"(a), "l"(b));
}

// ---------------- K0: dynamic Laplacian masks ----------------
__global__ __launch_bounds__(256)
void k0_masks(const float* __restrict__ mask1, const float* __restrict__ mask2) {
    int idx = blockIdx.x * 256 + threadIdx.x;
    int i = idx >> 6, j = idx & 63;
    float a = mask1[i * 64 + j] + mask1[j * 64 + i];
    g_m1[idx] = 0.5f / (1.f + expf(-a));
    float c = mask2[i * 64 + j] + mask2[j * 64 + i];
    g_m2[idx] = 0.5f / (1.f + expf(-c));
}

// ---------------- K1: per-batch conv+BN + 15-step SNN ----------------
// smem floats: sL1T@0(64x65 transposed) sL2T@4160(64x65) sy@8320(960)
// spar@9280(704) spkt@9984(64) spk1@10048(1024) sA@11072(1024; s_part overlays)
// total 12096 floats = 48384 B.  Conv phase reuses sL1T as sx, sL2T as scratch.
__global__ __launch_bounds__(256)
void k1_snn(const float* __restrict__ L_norm, const float* __restrict__ X_seq,
            const float* __restrict__ conv_w, const float* __restrict__ conv_b,
            const float* __restrict__ bn_gamma, const float* __restrict__ bn_beta,
            const float* __restrict__ bn_mean, const float* __restrict__ bn_var,
            const float* __restrict__ gcn1_w, const float* __restrict__ gcn1_b,
            const float* __restrict__ gcn2_w, const float* __restrict__ gcn2_b,
            const float* __restrict__ beta2p)
{
    extern __shared__ float sm[];
    float* sL1T  = sm;
    float* sL2T  = sm + 4160;
    float* sy    = sm + 8320;
    float* spar  = sm + 9280;
    float* s_spkt= sm + 9984;
    float* s_spk1= sm + 10048;
    float* s_A   = sm + 11072;
    float* s_part= s_A;          // overlay: part lives (b)->(g1), A lives (c)->(d)
    float* s_cx  = sm;           // conv-phase: x input in sL1T area
    float* s_scr = sm + 4160;    // conv-phase: partials in sL2T area

    const int tid = threadIdx.x;
    const int b = blockIdx.x;
    const float bt2 = beta2p[0];

    // --- load x + params ---
    for (int i = tid; i < 960; i += 256) s_cx[i] = X_seq[(size_t)b * 960 + i];
    if (tid < 16) { spar[tid] = gcn1_w[tid]; spar[16 + tid] = gcn1_b[tid]; }
    for (int i = tid; i < 512; i += 256) spar[32 + i] = gcn2_w[i];
    if (tid < 32) spar[544 + tid] = gcn2_b[tid];
    if (tid < 64) {
        float cs = bn_gamma[tid] * rsqrtf(bn_var[tid] + 1e-5f);
        spar[576 + tid] = cs;
        spar[640 + tid] = bn_beta[tid] + (conv_b[tid] - bn_mean[tid]) * cs;
    }
    __syncthreads();

    // --- causal conv1d: 4 threads per out-channel ---
    {
        const int c = tid & 63, q = tid >> 6, i0 = q * 16;
        float p[15];
        #pragma unroll
        for (int t = 0; t < 15; ++t) p[t] = 0.f;
        const float* wc = conv_w + (size_t)(c * 64 + i0) * 3;
        for (int ii = 0; ii < 16; ++ii) {
            float w0 = wc[ii * 3], w1 = wc[ii * 3 + 1], w2 = wc[ii * 3 + 2];
            const float* xc = s_cx + (i0 + ii);
            #pragma unroll
            for (int t = 0; t < 15; ++t) {
                float a = w2 * xc[t * 64];
                if (t >= 1) a += w1 * xc[(t - 1) * 64];
                if (t >= 2) a += w0 * xc[(t - 2) * 64];
                p[t] += a;
            }
        }
        #pragma unroll
        for (int t = 0; t < 15; ++t) s_scr[q * 960 + t * 64 + c] = p[t];
    }
    __syncthreads();
    for (int i = tid; i < 960; i += 256) {
        int c = i & 63;
        float v = s_scr[i] + s_scr[960 + i] + s_scr[1920 + i] + s_scr[2880 + i];
        sy[i] = v * spar[576 + c] + spar[640 + c];
    }
    __syncthreads();

    // --- load both masked Laplacians (transposed), one pass over L_norm ---
    const float* Lb = L_norm + (size_t)b * 4096;
    for (int i = tid; i < 4096; i += 256) {
        float l = Lb[i];
        int r = i >> 6, c = i & 63;
        sL1T[c * 65 + r] = l * g_m1[i];   // sL1T[j][i] = L[i][j]*m1
        sL2T[c * 65 + r] = l * g_m2[i];
    }

    // membrane states in registers
    float mt = 0.f;                       // used by tid<64
    float mg1r[4] = {0.f, 0.f, 0.f, 0.f};
    float mg2r[8] = {0.f, 0.f, 0.f, 0.f, 0.f, 0.f, 0.f, 0.f};
    __syncthreads();

    // (a) for t=0
    if (tid < 64) {
        float rst = (mt > 1.f) ? 1.f : 0.f;
        mt = 0.9f * mt + sy[tid] - rst;
        s_spkt[tid] = (mt > 1.f) ? 1.f : 0.f;
    }
    __syncthreads();

    const int iA = tid >> 2, gA = tid & 3, f0 = gA * 8;
    const int qb = tid >> 6, ib = tid & 63;

    for (int t = 0; t < 15; ++t) {
        // (b) partial s = L1 @ spk_t
        {
            float s = 0.f;
            #pragma unroll
            for (int j = 0; j < 16; ++j)
                s += sL1T[(qb * 16 + j) * 65 + ib] * s_spkt[qb * 16 + j];
            s_part[qb * 64 + ib] = s;
        }
        __syncthreads();
        // (g1) rank-1 GCN1 + LIF [64,16]
        #pragma unroll
        for (int v = 0; v < 4; ++v) {
            int e = tid + v * 256;
            int i = e >> 4, f = e & 15;
            float sv = s_part[i] + s_part[64 + i] + s_part[128 + i] + s_part[192 + i];
            float cur = sv * spar[f] + spar[16 + f];
            float m = mg1r[v];
            float rst = (m > 1.f) ? 1.f : 0.f;
            m = 0.85f * m + cur - rst;
            mg1r[v] = m;
            s_spk1[e] = (m > 1.f) ? 1.f : 0.f;
        }
        __syncthreads();
        // (c) A = L2 @ spk1   (f32x2)
        {
            unsigned long long a01 = 0ull, a23 = 0ull;
            #pragma unroll
            for (int j = 0; j < 64; ++j) {
                float l = sL2T[j * 65 + iA];
                unsigned long long lp = pk2(l, l);
                ulonglong2 s2 = *(const ulonglong2*)(s_spk1 + j * 16 + gA * 4);
                fma2(a01, lp, s2.x);
                fma2(a23, lp, s2.y);
            }
            float ax, ay, az, aw;
            upk2(a01, ax, ay); upk2(a23, az, aw);
            *(float4*)(s_A + iA * 16 + gA * 4) = make_float4(ax, ay, az, aw);
        }
        __syncthreads();
        // (d) cur2 = A @ W2 + b2 ; LIF ; emit pots ; then (a) for t+1
        {
            float4 b0 = *(const float4*)(spar + 544 + f0);
            float4 b1v = *(const float4*)(spar + 544 + f0 + 4);
            unsigned long long A01 = pk2(b0.x, b0.y), A23 = pk2(b0.z, b0.w);
            unsigned long long B01 = pk2(b1v.x, b1v.y), B23 = pk2(b1v.z, b1v.w);
            #pragma unroll
            for (int k = 0; k < 16; ++k) {
                float av = s_A[iA * 16 + k];
                unsigned long long ap = pk2(av, av);
                ulonglong2 wa = *(const ulonglong2*)(spar + 32 + k * 32 + f0);
                ulonglong2 wb = *(const ulonglong2*)(spar + 32 + k * 32 + f0 + 4);
                fma2(A01, ap, wa.x); fma2(A23, ap, wa.y);
                fma2(B01, ap, wb.x); fma2(B23, ap, wb.y);
            }
            float cv[8];
            upk2(A01, cv[0], cv[1]); upk2(A23, cv[2], cv[3]);
            upk2(B01, cv[4], cv[5]); upk2(B23, cv[6], cv[7]);
            float ov[8];
            #pragma unroll
            for (int u = 0; u < 8; ++u) {
                float m = mg2r[u];
                float rst = (m > 1.f) ? 1.f : 0.f;
                m = bt2 * m + cv[u] - rst;
                mg2r[u] = m; ov[u] = m;
            }
            float* gp = g_pots + (size_t)(b * 15 + t) * 2048 + iA * 32 + f0;
            *(float4*)gp = make_float4(ov[0], ov[1], ov[2], ov[3]);
            *(float4*)(gp + 4) = make_float4(ov[4], ov[5], ov[6], ov[7]);
            if (t < 14 && tid < 64) {
                float rst = (mt > 1.f) ? 1.f : 0.f;
                mt = 0.9f * mt + sy[(t + 1) * 64 + tid] - rst;
                s_spkt[tid] = (mt > 1.f) ? 1.f : 0.f;
            }
        }
        __syncthreads();
    }
}

// ---------------- K2: fused scores GEMM + softmax + context ----------------
// tile = 120 rows = 8 batches per CTA; grid 512.  warp rg <-> batch rg.
__global__ __launch_bounds__(256)
void k2_fused(const float* __restrict__ W1, const float* __restrict__ b1,
              const float* __restrict__ w2, const float* __restrict__ b2)
{
    __shared__ float sP[120 * 64];
    __shared__ float sW[64 * 32];
    __shared__ float ssc[8 * 16];
    const int tid = threadIdx.x;
    const int f = tid & 31, rg = tid >> 5;
    const size_t rb = (size_t)blockIdx.x * 120;

    unsigned long long acc2[15];
    #pragma unroll
    for (int t = 0; t < 15; ++t) acc2[t] = 0ull;

    for (int kc = 0; kc < 32; ++kc) {
        __syncthreads();
        #pragma unroll
        for (int v = 0; v < 30; ++v) {
            int idx = tid + v * 256;
            sP[idx] = g_pots[(rb + (idx >> 6)) * 2048 + kc * 64 + (idx & 63)];
        }
        #pragma unroll
        for (int v = 0; v < 8; ++v) {
            int idx = tid + v * 256;
            sW[idx] = W1[(size_t)(kc * 64 + (idx >> 5)) * 32 + (idx & 31)];
        }
        __syncthreads();
        #pragma unroll
        for (int j4 = 0; j4 < 16; ++j4) {
            float w0 = sW[(j4 * 4 + 0) * 32 + f];
            float w1v = sW[(j4 * 4 + 1) * 32 + f];
            float w2v = sW[(j4 * 4 + 2) * 32 + f];
            float w3v = sW[(j4 * 4 + 3) * 32 + f];
            unsigned long long w01 = pk2(w0, w1v), w23 = pk2(w2v, w3v);
            #pragma unroll
            for (int t = 0; t < 15; ++t) {
                ulonglong2 p = *(const ulonglong2*)(sP + (rg * 15 + t) * 64 + j4 * 4);
                fma2(acc2[t], p.x, w01);
                fma2(acc2[t], p.y, w23);
            }
        }
    }
    // scores: tanh(acc + b1) @ w2 (+b2), reduce over f
    float b1f = b1[f], w2f = w2[f], b2s = b2[0];
    #pragma unroll
    for (int t = 0; t < 15; ++t) {
        float lo, hi; upk2(acc2[t], lo, hi);
        float v = tanhf(lo + hi + b1f) * w2f;
        v += __shfl_xor_sync(0xffffffffu, v, 16);
        v += __shfl_xor_sync(0xffffffffu, v, 8);
        v += __shfl_xor_sync(0xffffffffu, v, 4);
        v += __shfl_xor_sync(0xffffffffu, v, 2);
        v += __shfl_xor_sync(0xffffffffu, v, 1);
        if (f == 0) ssc[rg * 16 + t] = v + b2s;
    }
    __syncthreads();
    // per-warp softmax over T
    float w[15];
    float mx = ssc[rg * 16];
    #pragma unroll
    for (int t = 1; t < 15; ++t) mx = fmaxf(mx, ssc[rg * 16 + t]);
    float se = 0.f;
    #pragma unroll
    for (int t = 0; t < 15; ++t) { w[t] = expf(ssc[rg * 16 + t] - mx); se += w[t]; }
    float inv = 1.f / se;
    // context: warp rg handles batch b (pots rows are L2-hot)
    const size_t bb = (size_t)blockIdx.x * 8 + rg;
    const float* pb = g_pots + bb * 15 * 2048;
    float* cb = g_ctx + bb * 2048;
    #pragma unroll 4
    for (int e0 = 0; e0 < 16; ++e0) {
        float4 a4 = make_float4(0.f, 0.f, 0.f, 0.f);
        #pragma unroll
        for (int t = 0; t < 15; ++t) {
            float4 p = *(const float4*)(pb + t * 2048 + e0 * 128 + f * 4);
            a4.x += w[t] * p.x; a4.y += w[t] * p.y;
            a4.z += w[t] * p.z; a4.w += w[t] * p.w;
        }
        *(float4*)(cb + e0 * 128 + f * 4) =
            make_float4(a4.x * inv, a4.y * inv, a4.z * inv, a4.w * inv);
    }
}

// ---------------- K4: classifier + LN + GELU + final ----------------
__global__ __launch_bounds__(256)
void k4_cls(const float* __restrict__ W1, const float* __restrict__ b1,
            const float* __restrict__ lng, const float* __restrict__ lnb,
            const float* __restrict__ W2, const float* __restrict__ b2,
            float* __restrict__ out)
{
    __shared__ float sC[16 * 68];
    __shared__ float sW[64 * 128];
    __shared__ float sH[16 * 132];
    const int tid = threadIdx.x;
    const int rb = blockIdx.x * 16;
    const int r = tid >> 4, cg = tid & 15;
    unsigned long long acc2[4] = {0ull, 0ull, 0ull, 0ull};

    for (int ch = 0; ch < 32; ++ch) {
        __syncthreads();
        for (int i = tid; i < 1024; i += 256) {
            int rr = i >> 6, kk = i & 63;
            sC[rr * 68 + kk] = g_ctx[(size_t)(rb + rr) * 2048 + ch * 64 + kk];
        }
        for (int i = tid; i < 8192; i += 256)
            sW[i] = W1[(size_t)(ch * 64 + (i >> 7)) * 128 + (i & 127)];
        __syncthreads();
        #pragma unroll 8
        for (int k = 0; k < 64; ++k) {
            float a = sC[r * 68 + k];
            unsigned long long ap = pk2(a, a);
            ulonglong2 w0 = *(const ulonglong2*)(sW + k * 128 + cg * 8);
            ulonglong2 w1 = *(const ulonglong2*)(sW + k * 128 + cg * 8 + 4);
            fma2(acc2[0], ap, w0.x); fma2(acc2[1], ap, w0.y);
            fma2(acc2[2], ap, w1.x); fma2(acc2[3], ap, w1.y);
        }
    }
    float acc[8];
    upk2(acc2[0], acc[0], acc[1]); upk2(acc2[1], acc[2], acc[3]);
    upk2(acc2[2], acc[4], acc[5]); upk2(acc2[3], acc[6], acc[7]);
    __syncthreads();
    #pragma unroll
    for (int u = 0; u < 8; ++u) sH[r * 132 + cg * 8 + u] = acc[u] + b1[cg * 8 + u];
    __syncthreads();
    {
        float s = 0.f, s2 = 0.f;
        #pragma unroll
        for (int u = 0; u < 8; ++u) {
            float v = sH[r * 132 + cg * 8 + u];
            s += v; s2 += v * v;
        }
        #pragma unroll
        for (int o = 8; o >= 1; o >>= 1) {
            s += __shfl_xor_sync(0xffffffffu, s, o);
            s2 += __shfl_xor_sync(0xffffffffu, s2, o);
        }
        float mu = s * (1.f / 128.f);
        float var = s2 * (1.f / 128.f) - mu * mu;
        float rstd = rsqrtf(var + 1e-5f);
        #pragma unroll
        for (int u = 0; u < 8; ++u) {
            int c = cg * 8 + u;
            float v = (sH[r * 132 + c] - mu) * rstd * lng[c] + lnb[c];
            v = 0.5f * v * (1.f + erff(v * 0.70710678118654752440f));
            sH[r * 132 + c] = v;
        }
    }
    __syncthreads();
    if (tid < 64) {
        int rr = tid >> 2, o = tid & 3;
        float a = b2[o];
        #pragma unroll 16
        for (int c = 0; c < 128; ++c) a += sH[rr * 132 + c] * W2[c * 4 + o];
        out[(size_t)(rb + rr) * 4 + o] = a;
    }
}

extern "C" void kernel_launch(void* const* d_in, const int* in_sizes, int n_in,
                              void* d_out, int out_size) {
    (void)in_sizes; (void)n_in; (void)out_size;
    const float* L_norm  = (const float*)d_in[0];
    const float* X_seq   = (const float*)d_in[1];
    const float* conv_w  = (const float*)d_in[2];
    const float* conv_b  = (const float*)d_in[3];
    const float* bn_g    = (const float*)d_in[4];
    const float* bn_b    = (const float*)d_in[5];
    const float* bn_m    = (const float*)d_in[6];
    const float* bn_v    = (const float*)d_in[7];
    const float* g1w     = (const float*)d_in[8];
    const float* g1b     = (const float*)d_in[9];
    const float* mask1   = (const float*)d_in[10];
    const float* g2w     = (const float*)d_in[11];
    const float* g2b     = (const float*)d_in[12];
    const float* mask2   = (const float*)d_in[13];
    const float* beta2   = (const float*)d_in[14];
    const float* aw1     = (const float*)d_in[15];
    const float* ab1     = (const float*)d_in[16];
    const float* aw2     = (const float*)d_in[17];
    const float* ab2     = (const float*)d_in[18];
    const float* cw1     = (const float*)d_in[19];
    const float* cb1     = (const float*)d_in[20];
    const float* lng     = (const float*)d_in[21];
    const float* lnb     = (const float*)d_in[22];
    const float* cw2     = (const float*)d_in[23];
    const float* cb2     = (const float*)d_in[24];
    float* out = (float*)d_out;

    k0_masks<<<16, 256>>>(mask1, mask2);
    k1_snn<<<4096, 256, 48384>>>(L_norm, X_seq, conv_w, conv_b, bn_g, bn_b,
                                 bn_m, bn_v, g1w, g1b, g2w, g2b, beta2);
    k2_fused<<<512, 256>>>(aw1, ab1, aw2, ab2);
    k4_cls<<<256, 256>>>(cw1, cb1, lng, lnb, cw2, cb2, out);
}

// round 8
// speedup vs baseline: 2.0825x; 1.2032x over previous
#include <cuda_runtime.h>
#include <math.h>

__device__ float g_m1[4096];
__device__ float g_m2[4096];
__device__ float g_pots[125829120];   // [B*T, 2048]
__device__ float g_ctx[8388608];      // [B, 2048]

// ---- packed f32x2 helpers (Blackwell) ----
__device__ __forceinline__ unsigned long long pk2(float lo, float hi) {
    unsigned long long r;
    asm("mov.b64 %0, {%1, %2};" : "=l"(r) : "f"(lo), "f"(hi));
    return r;
}
__device__ __forceinline__ void upk2(unsigned long long v, float& lo, float& hi) {
    asm("mov.b64 {%0, %1}, %2;" : "=f"(lo), "=f"(hi) : "l"(v));
}
__device__ __forceinline__ void fma2(unsigned long long& d, unsigned long long a,
                                     unsigned long long b) {
    asm("fma.rn.f32x2 %0, %1, %2, %0;" : "+l"(d) : "l"(a), "l"(b));
}

// ---------------- K0: dynamic Laplacian masks ----------------
__global__ __launch_bounds__(256)
void k0_masks(const float* __restrict__ mask1, const float* __restrict__ mask2) {
    int idx = blockIdx.x * 256 + threadIdx.x;
    int i = idx >> 6, j = idx & 63;
    float a = mask1[i * 64 + j] + mask1[j * 64 + i];
    g_m1[idx] = 0.5f / (1.f + expf(-a));
    float c = mask2[i * 64 + j] + mask2[j * 64 + i];
    g_m2[idx] = 0.5f / (1.f + expf(-c));
}

// ---------------- K1: per-batch conv+BN + 15-step SNN ----------------
// smem floats: sL1T@0(64x65 transposed)  sL2@4160(64x68 row-major padded)
// sy@8512(960) spar@9472(704) spkt@10176(64) spk1@10240(1024)
// sAT@11264(16x65=1040; s_part(1024) overlays)  total 12304 floats = 49216 B
// Conv phase reuses sL1T region as sx, sL2 region as scratch.
__global__ __launch_bounds__(256)
void k1_snn(const float* __restrict__ L_norm, const float* __restrict__ X_seq,
            const float* __restrict__ conv_w, const float* __restrict__ conv_b,
            const float* __restrict__ bn_gamma, const float* __restrict__ bn_beta,
            const float* __restrict__ bn_mean, const float* __restrict__ bn_var,
            const float* __restrict__ gcn1_w, const float* __restrict__ gcn1_b,
            const float* __restrict__ gcn2_w, const float* __restrict__ gcn2_b,
            const float* __restrict__ beta2p)
{
    extern __shared__ float sm[];
    float* sL1T  = sm;
    float* sL2   = sm + 4160;
    float* sy    = sm + 8512;
    float* spar  = sm + 9472;
    float* s_spkt= sm + 10176;
    float* s_spk1= sm + 10240;
    float* sAT   = sm + 11264;
    float* s_part= sAT;          // overlay: part lives (b)->(g1), A lives (c)->(d)
    float* s_cx  = sm;           // conv-phase: x input in sL1T area
    float* s_scr = sm + 4160;    // conv-phase: partials in sL2 area

    const int tid = threadIdx.x;
    const int b = blockIdx.x;
    const float bt2 = beta2p[0];

    // --- load x + params ---
    for (int i = tid; i < 960; i += 256) s_cx[i] = X_seq[(size_t)b * 960 + i];
    if (tid < 16) { spar[tid] = gcn1_w[tid]; spar[16 + tid] = gcn1_b[tid]; }
    for (int i = tid; i < 512; i += 256) spar[32 + i] = gcn2_w[i];
    if (tid < 32) spar[544 + tid] = gcn2_b[tid];
    if (tid < 64) {
        float cs = bn_gamma[tid] * rsqrtf(bn_var[tid] + 1e-5f);
        spar[576 + tid] = cs;
        spar[640 + tid] = bn_beta[tid] + (conv_b[tid] - bn_mean[tid]) * cs;
    }
    __syncthreads();

    // --- causal conv1d: 4 threads per out-channel ---
    {
        const int c = tid & 63, q = tid >> 6, i0 = q * 16;
        float p[15];
        #pragma unroll
        for (int t = 0; t < 15; ++t) p[t] = 0.f;
        const float* wc = conv_w + (size_t)(c * 64 + i0) * 3;
        #pragma unroll 4
        for (int ii = 0; ii < 16; ++ii) {
            float w0 = wc[ii * 3], w1 = wc[ii * 3 + 1], w2 = wc[ii * 3 + 2];
            const float* xc = s_cx + (i0 + ii);
            #pragma unroll
            for (int t = 0; t < 15; ++t) {
                float a = w2 * xc[t * 64];
                if (t >= 1) a += w1 * xc[(t - 1) * 64];
                if (t >= 2) a += w0 * xc[(t - 2) * 64];
                p[t] += a;
            }
        }
        #pragma unroll
        for (int t = 0; t < 15; ++t) s_scr[q * 960 + t * 64 + c] = p[t];
    }
    __syncthreads();
    for (int i = tid; i < 960; i += 256) {
        int c = i & 63;
        float v = s_scr[i] + s_scr[960 + i] + s_scr[1920 + i] + s_scr[2880 + i];
        sy[i] = v * spar[576 + c] + spar[640 + c];
    }
    __syncthreads();

    // --- load both masked Laplacians, one pass over L_norm ---
    const float* Lb = L_norm + (size_t)b * 4096;
    #pragma unroll 4
    for (int i = tid; i < 4096; i += 256) {
        float l = Lb[i];
        int r = i >> 6, c = i & 63;
        sL1T[c * 65 + r] = l * g_m1[i];   // transposed for phase (b)
        sL2 [r * 68 + c] = l * g_m2[i];   // row-major padded for phase (c) float4 reads
    }

    // membrane states in registers
    float mt = 0.f;
    float mg1r[4] = {0.f, 0.f, 0.f, 0.f};
    float mg2r[8] = {0.f, 0.f, 0.f, 0.f, 0.f, 0.f, 0.f, 0.f};
    __syncthreads();

    // (a) for t=0
    if (tid < 64) {
        float rst = (mt > 1.f) ? 1.f : 0.f;
        mt = 0.9f * mt + sy[tid] - rst;
        s_spkt[tid] = (mt > 1.f) ? 1.f : 0.f;
    }
    __syncthreads();

    const int iA = tid >> 2, gA = tid & 3, f0 = gA * 8;
    const int qb = tid >> 6, ib = tid & 63;

    for (int t = 0; t < 15; ++t) {
        // (b) partial s = L1 @ spk_t
        {
            float s = 0.f;
            #pragma unroll
            for (int j = 0; j < 16; ++j)
                s += sL1T[(qb * 16 + j) * 65 + ib] * s_spkt[qb * 16 + j];
            s_part[qb * 64 + ib] = s;
        }
        __syncthreads();
        // (g1) rank-1 GCN1 + LIF [64,16]
        #pragma unroll
        for (int v = 0; v < 4; ++v) {
            int e = tid + v * 256;
            int i = e >> 4, f = e & 15;
            float sv = s_part[i] + s_part[64 + i] + s_part[128 + i] + s_part[192 + i];
            float cur = sv * spar[f] + spar[16 + f];
            float m = mg1r[v];
            float rst = (m > 1.f) ? 1.f : 0.f;
            m = 0.85f * m + cur - rst;
            mg1r[v] = m;
            s_spk1[e] = (m > 1.f) ? 1.f : 0.f;
        }
        __syncthreads();
        // (c) A = L2 @ spk1  (float4 L-row loads, f32x2 accum; same j order)
        {
            unsigned long long a01 = 0ull, a23 = 0ull;
            #pragma unroll
            for (int j4 = 0; j4 < 16; ++j4) {
                float4 l4 = *(const float4*)(sL2 + iA * 68 + j4 * 4);
                ulonglong2 s0 = *(const ulonglong2*)(s_spk1 + (j4 * 4 + 0) * 16 + gA * 4);
                unsigned long long lp = pk2(l4.x, l4.x);
                fma2(a01, lp, s0.x); fma2(a23, lp, s0.y);
                ulonglong2 s1 = *(const ulonglong2*)(s_spk1 + (j4 * 4 + 1) * 16 + gA * 4);
                lp = pk2(l4.y, l4.y);
                fma2(a01, lp, s1.x); fma2(a23, lp, s1.y);
                ulonglong2 s2 = *(const ulonglong2*)(s_spk1 + (j4 * 4 + 2) * 16 + gA * 4);
                lp = pk2(l4.z, l4.z);
                fma2(a01, lp, s2.x); fma2(a23, lp, s2.y);
                ulonglong2 s3 = *(const ulonglong2*)(s_spk1 + (j4 * 4 + 3) * 16 + gA * 4);
                lp = pk2(l4.w, l4.w);
                fma2(a01, lp, s3.x); fma2(a23, lp, s3.y);
            }
            float ax, ay, az, aw;
            upk2(a01, ax, ay); upk2(a23, az, aw);
            sAT[(gA * 4 + 0) * 65 + iA] = ax;   // transposed store: (d) reads conflict-free
            sAT[(gA * 4 + 1) * 65 + iA] = ay;
            sAT[(gA * 4 + 2) * 65 + iA] = az;
            sAT[(gA * 4 + 3) * 65 + iA] = aw;
        }
        __syncthreads();
        // (d) cur2 = A @ W2 + b2 ; LIF ; emit pots ; then (a) for t+1
        {
            float4 b0 = *(const float4*)(spar + 544 + f0);
            float4 b1v = *(const float4*)(spar + 544 + f0 + 4);
            unsigned long long A01 = pk2(b0.x, b0.y), A23 = pk2(b0.z, b0.w);
            unsigned long long B01 = pk2(b1v.x, b1v.y), B23 = pk2(b1v.z, b1v.w);
            #pragma unroll
            for (int k = 0; k < 16; ++k) {
                float av = sAT[k * 65 + iA];
                unsigned long long ap = pk2(av, av);
                ulonglong2 wa = *(const ulonglong2*)(spar + 32 + k * 32 + f0);
                ulonglong2 wb = *(const ulonglong2*)(spar + 32 + k * 32 + f0 + 4);
                fma2(A01, ap, wa.x); fma2(A23, ap, wa.y);
                fma2(B01, ap, wb.x); fma2(B23, ap, wb.y);
            }
            float cv[8];
            upk2(A01, cv[0], cv[1]); upk2(A23, cv[2], cv[3]);
            upk2(B01, cv[4], cv[5]); upk2(B23, cv[6], cv[7]);
            float ov[8];
            #pragma unroll
            for (int u = 0; u < 8; ++u) {
                float m = mg2r[u];
                float rst = (m > 1.f) ? 1.f : 0.f;
                m = bt2 * m + cv[u] - rst;
                mg2r[u] = m; ov[u] = m;
            }
            float* gp = g_pots + (size_t)(b * 15 + t) * 2048 + iA * 32 + f0;
            *(float4*)gp = make_float4(ov[0], ov[1], ov[2], ov[3]);
            *(float4*)(gp + 4) = make_float4(ov[4], ov[5], ov[6], ov[7]);
            if (t < 14 && tid < 64) {
                float rst = (mt > 1.f) ? 1.f : 0.f;
                mt = 0.9f * mt + sy[(t + 1) * 64 + tid] - rst;
                s_spkt[tid] = (mt > 1.f) ? 1.f : 0.f;
            }
        }
        __syncthreads();
    }
}

// ---------------- K2: fused scores GEMM + softmax + context ----------------
// tile = 120 rows = 8 batches per CTA; grid 512.  warp rg <-> batch rg.
__global__ __launch_bounds__(256)
void k2_fused(const float* __restrict__ W1, const float* __restrict__ b1,
              const float* __restrict__ w2, const float* __restrict__ b2)
{
    __shared__ float sP[120 * 64];
    __shared__ float sW[64 * 32];
    __shared__ float ssc[8 * 16];
    const int tid = threadIdx.x;
    const int f = tid & 31, rg = tid >> 5;
    const size_t rb = (size_t)blockIdx.x * 120;

    unsigned long long acc2[15];
    #pragma unroll
    for (int t = 0; t < 15; ++t) acc2[t] = 0ull;

    for (int kc = 0; kc < 32; ++kc) {
        __syncthreads();
        #pragma unroll
        for (int v = 0; v < 30; ++v) {
            int idx = tid + v * 256;
            sP[idx] = g_pots[(rb + (idx >> 6)) * 2048 + kc * 64 + (idx & 63)];
        }
        #pragma unroll
        for (int v = 0; v < 8; ++v) {
            int idx = tid + v * 256;
            sW[idx] = W1[(size_t)(kc * 64 + (idx >> 5)) * 32 + (idx & 31)];
        }
        __syncthreads();
        #pragma unroll
        for (int j4 = 0; j4 < 16; ++j4) {
            float w0 = sW[(j4 * 4 + 0) * 32 + f];
            float w1v = sW[(j4 * 4 + 1) * 32 + f];
            float w2v = sW[(j4 * 4 + 2) * 32 + f];
            float w3v = sW[(j4 * 4 + 3) * 32 + f];
            unsigned long long w01 = pk2(w0, w1v), w23 = pk2(w2v, w3v);
            #pragma unroll
            for (int t = 0; t < 15; ++t) {
                ulonglong2 p = *(const ulonglong2*)(sP + (rg * 15 + t) * 64 + j4 * 4);
                fma2(acc2[t], p.x, w01);
                fma2(acc2[t], p.y, w23);
            }
        }
    }
    float b1f = b1[f], w2f = w2[f], b2s = b2[0];
    #pragma unroll
    for (int t = 0; t < 15; ++t) {
        float lo, hi; upk2(acc2[t], lo, hi);
        float v = tanhf(lo + hi + b1f) * w2f;
        v += __shfl_xor_sync(0xffffffffu, v, 16);
        v += __shfl_xor_sync(0xffffffffu, v, 8);
        v += __shfl_xor_sync(0xffffffffu, v, 4);
        v += __shfl_xor_sync(0xffffffffu, v, 2);
        v += __shfl_xor_sync(0xffffffffu, v, 1);
        if (f == 0) ssc[rg * 16 + t] = v + b2s;
    }
    __syncthreads();
    float w[15];
    float mx = ssc[rg * 16];
    #pragma unroll
    for (int t = 1; t < 15; ++t) mx = fmaxf(mx, ssc[rg * 16 + t]);
    float se = 0.f;
    #pragma unroll
    for (int t = 0; t < 15; ++t) { w[t] = expf(ssc[rg * 16 + t] - mx); se += w[t]; }
    float inv = 1.f / se;
    const size_t bb = (size_t)blockIdx.x * 8 + rg;
    const float* pb = g_pots + bb * 15 * 2048;
    float* cb = g_ctx + bb * 2048;
    #pragma unroll 4
    for (int e0 = 0; e0 < 16; ++e0) {
        float4 a4 = make_float4(0.f, 0.f, 0.f, 0.f);
        #pragma unroll
        for (int t = 0; t < 15; ++t) {
            float4 p = *(const float4*)(pb + t * 2048 + e0 * 128 + f * 4);
            a4.x += w[t] * p.x; a4.y += w[t] * p.y;
            a4.z += w[t] * p.z; a4.w += w[t] * p.w;
        }
        *(float4*)(cb + e0 * 128 + f * 4) =
            make_float4(a4.x * inv, a4.y * inv, a4.z * inv, a4.w * inv);
    }
}

// ---------------- K4: classifier + LN + GELU + final (rewritten) ----------------
// 16 rows/CTA (grid 256), 256 thr.  warp w <-> rows {2w, 2w+1}; lane = 4 cols.
// float4 staging fully unrolled; thread-block 2 rows x 4 cols (4 fma2 per k).
__global__ __launch_bounds__(256)
void k4_cls(const float* __restrict__ W1, const float* __restrict__ b1,
            const float* __restrict__ lng, const float* __restrict__ lnb,
            const float* __restrict__ W2, const float* __restrict__ b2,
            float* __restrict__ out)
{
    __shared__ float sC[16 * 68];     // row tile, padded
    __shared__ float sW[64 * 128];    // weight chunk
    __shared__ float sH[16 * 132];
    const int tid = threadIdx.x;
    const int rb = blockIdx.x * 16;
    const int ci = tid & 31, ri = tid >> 5;     // warp ri: rows 2ri, 2ri+1
    const int r0 = ri * 2;
    unsigned long long acc[4] = {0ull, 0ull, 0ull, 0ull};  // 2 rows x (2 col-pairs)

    const int scr = tid >> 4, scq = tid & 15;   // sC staging: 1 float4/thread
    for (int ch = 0; ch < 32; ++ch) {
        __syncthreads();
        {
            float4 cv = *(const float4*)(g_ctx + (size_t)(rb + scr) * 2048 + ch * 64 + scq * 4);
            *(float4*)(sC + scr * 68 + scq * 4) = cv;
        }
        #pragma unroll
        for (int v = 0; v < 8; ++v) {
            int e4 = tid + v * 256;             // float4 index into 64x128 tile
            *(float4*)(sW + e4 * 4) =
                *(const float4*)(W1 + (size_t)(ch * 64 + (e4 >> 5)) * 128 + (e4 & 31) * 4);
        }
        __syncthreads();
        #pragma unroll 8
        for (int k = 0; k < 64; ++k) {
            float a0 = sC[r0 * 68 + k];
            float a1 = sC[(r0 + 1) * 68 + k];
            ulonglong2 wv = *(const ulonglong2*)(sW + k * 128 + ci * 4);
            unsigned long long p0 = pk2(a0, a0), p1 = pk2(a1, a1);
            fma2(acc[0], p0, wv.x); fma2(acc[1], p0, wv.y);
            fma2(acc[2], p1, wv.x); fma2(acc[3], p1, wv.y);
        }
    }
    __syncthreads();
    {
        float h[8];
        upk2(acc[0], h[0], h[1]); upk2(acc[1], h[2], h[3]);
        upk2(acc[2], h[4], h[5]); upk2(acc[3], h[6], h[7]);
        float4 bb0 = *(const float4*)(b1 + ci * 4);
        sH[r0 * 132 + ci * 4 + 0] = h[0] + bb0.x;
        sH[r0 * 132 + ci * 4 + 1] = h[1] + bb0.y;
        sH[r0 * 132 + ci * 4 + 2] = h[2] + bb0.z;
        sH[r0 * 132 + ci * 4 + 3] = h[3] + bb0.w;
        sH[(r0 + 1) * 132 + ci * 4 + 0] = h[4] + bb0.x;
        sH[(r0 + 1) * 132 + ci * 4 + 1] = h[5] + bb0.y;
        sH[(r0 + 1) * 132 + ci * 4 + 2] = h[6] + bb0.z;
        sH[(r0 + 1) * 132 + ci * 4 + 3] = h[7] + bb0.w;
    }
    __syncwarp();
    // LayerNorm + GELU per row (warp handles its 2 rows; full-warp butterflies)
    #pragma unroll
    for (int rr = 0; rr < 2; ++rr) {
        int row = r0 + rr;
        float s = 0.f, s2 = 0.f;
        #pragma unroll
        for (int u = 0; u < 4; ++u) {
            float v = sH[row * 132 + ci * 4 + u];
            s += v; s2 += v * v;
        }
        #pragma unroll
        for (int o = 16; o >= 1; o >>= 1) {
            s += __shfl_xor_sync(0xffffffffu, s, o);
            s2 += __shfl_xor_sync(0xffffffffu, s2, o);
        }
        float mu = s * (1.f / 128.f);
        float var = s2 * (1.f / 128.f) - mu * mu;
        float rstd = rsqrtf(var + 1e-5f);
        #pragma unroll
        for (int u = 0; u < 4; ++u) {
            int c = ci * 4 + u;
            float v = (sH[row * 132 + c] - mu) * rstd * lng[c] + lnb[c];
            v = 0.5f * v * (1.f + erff(v * 0.70710678118654752440f));
            sH[row * 132 + c] = v;
        }
    }
    __syncthreads();
    if (tid < 64) {
        int rr = tid >> 2, o = tid & 3;
        float a = b2[o];
        #pragma unroll 16
        for (int c = 0; c < 128; ++c) a += sH[rr * 132 + c] * W2[c * 4 + o];
        out[(size_t)(rb + rr) * 4 + o] = a;
    }
}

extern "C" void kernel_launch(void* const* d_in, const int* in_sizes, int n_in,
                              void* d_out, int out_size) {
    (void)in_sizes; (void)n_in; (void)out_size;
    const float* L_norm  = (const float*)d_in[0];
    const float* X_seq   = (const float*)d_in[1];
    const float* conv_w  = (const float*)d_in[2];
    const float* conv_b  = (const float*)d_in[3];
    const float* bn_g    = (const float*)d_in[4];
    const float* bn_b    = (const float*)d_in[5];
    const float* bn_m    = (const float*)d_in[6];
    const float* bn_v    = (const float*)d_in[7];
    const float* g1w     = (const float*)d_in[8];
    const float* g1b     = (const float*)d_in[9];
    const float* mask1   = (const float*)d_in[10];
    const float* g2w     = (const float*)d_in[11];
    const float* g2b     = (const float*)d_in[12];
    const float* mask2   = (const float*)d_in[13];
    const float* beta2   = (const float*)d_in[14];
    const float* aw1     = (const float*)d_in[15];
    const float* ab1     = (const float*)d_in[16];
    const float* aw2     = (const float*)d_in[17];
    const float* ab2     = (const float*)d_in[18];
    const float* cw1     = (const float*)d_in[19];
    const float* cb1     = (const float*)d_in[20];
    const float* lng     = (const float*)d_in[21];
    const float* lnb     = (const float*)d_in[22];
    const float* cw2     = (const float*)d_in[23];
    const float* cb2     = (const float*)d_in[24];
    float* out = (float*)d_out;

    cudaFuncSetAttribute(k1_snn, cudaFuncAttributeMaxDynamicSharedMemorySize, 49216);

    k0_masks<<<16, 256>>>(mask1, mask2);
    k1_snn<<<4096, 256, 49216>>>(L_norm, X_seq, conv_w, conv_b, bn_g, bn_b,
                                 bn_m, bn_v, g1w, g1b, g2w, g2b, beta2);
    k2_fused<<<512, 256>>>(aw1, ab1, aw2, ab2);
    k4_cls<<<256, 256>>>(cw1, cb1, lng, lnb, cw2, cb2, out);
}